// round 10
// baseline (speedup 1.0000x reference)
#include <cuda_runtime.h>

#define NN 100000
#define NE 3200000
#define DF 512
#define HID 16
#define NC  40
#define SCAN_CHUNK 1024
#define NB ((NN + SCAN_CHUNK - 1) / SCAN_CHUNK)   // 98

typedef unsigned long long ull;

// ---------------- device scratch ----------------
__device__ ull   g_pack[NN];   // (cnt << 40) | fixed20(weighted degree)
__device__ float g_dinv[NN];   // d^-1/2
__device__ int   g_cnt[NN];    // in-degree (edges only)
__device__ int   g_ptr[NN];    // CSR offsets; after build: end offsets
__device__ int2  g_edge[NE];   // (src, w-as-int) per CSR slot
__device__ float g_hx [NN * HID];
__device__ float g_h1 [NN * HID];
__device__ int   g_part[NB];

#define FMA2(d, a, b) asm("fma.rn.f32x2 %0, %1, %2, %0;" : "+l"(d) : "l"(a), "l"(b))
#define MUL2(d, a, b) asm("mul.rn.f32x2 %0, %1, %2;" : "=l"(d) : "l"(a), "l"(b))

// ---------------- 0: init ----------------
__global__ void k_init(int n) {
    int i = blockIdx.x * blockDim.x + threadIdx.x;
    if (i < n) g_pack[i] = (1ULL << 20);   // self-loop w=1.0 in fixed20, cnt=0
}

// ---------------- 1: pass1 — single packed 64-bit atomic per edge ----------------
__global__ void __launch_bounds__(256) k_pass1(const int* __restrict__ col,
                                               const float* __restrict__ w, int E) {
    long i0 = ((long)blockIdx.x * blockDim.x + threadIdx.x) * 4;
    if (i0 >= E) return;
    if (i0 + 3 < E) {
        int4   c4 = *(const int4*)  (col + i0);
        float4 w4 = *(const float4*)(w   + i0);
        atomicAdd(&g_pack[c4.x], (1ULL << 40) + (ull)(w4.x * 1048576.0f + 0.5f));
        atomicAdd(&g_pack[c4.y], (1ULL << 40) + (ull)(w4.y * 1048576.0f + 0.5f));
        atomicAdd(&g_pack[c4.z], (1ULL << 40) + (ull)(w4.z * 1048576.0f + 0.5f));
        atomicAdd(&g_pack[c4.w], (1ULL << 40) + (ull)(w4.w * 1048576.0f + 0.5f));
    } else {
        for (long k = i0; k < E; k++)
            atomicAdd(&g_pack[col[k]], (1ULL << 40) + (ull)(w[k] * 1048576.0f + 0.5f));
    }
}

// ---------------- 2: scanA — unpack, rsqrt, per-chunk sums ----------------
__global__ void k_scanA(int n) {
    __shared__ int sh[256];
    int t = threadIdx.x;
    int base = blockIdx.x * SCAN_CHUNK;
    int s = 0;
    #pragma unroll
    for (int k = 0; k < 4; k++) {
        int idx = base + t + k * 256;
        if (idx < n) {
            ull p = g_pack[idx];
            int cnt = (int)(p >> 40);
            float deg = (float)(p & ((1ULL << 40) - 1)) * (1.0f / 1048576.0f);
            g_cnt[idx]  = cnt;
            g_dinv[idx] = rsqrtf(deg);
            s += cnt;
        }
    }
    sh[t] = s;
    __syncthreads();
    for (int off = 128; off > 0; off >>= 1) {
        if (t < off) sh[t] += sh[t + off];
        __syncthreads();
    }
    if (t == 0) g_part[blockIdx.x] = sh[0];
}

// ---------------- 3: GEMM1 (PROFILED) — g_hx = dinv[row] * (x @ W1) ----------------
// 64 threads = 2 warps; R=2 rows per thread (64 rows/warp, 128 rows/block).
// Same per-warp structure as before; smaller block -> 5 blocks/SM co-resident
// (smem 40.5 KB) and grid 782 -> ~20 warps/SM (occupancy was the binder at 391x50KB).
__global__ void __launch_bounds__(64) k_gemm1(const float* __restrict__ x,
                                              const float* __restrict__ W1, int n) {
    extern __shared__ char smraw[];
    ull*   Ws = (ull*)smraw;                     // 32 KB: Ws[k*8+p] = W1[k*16+2p..2p+1]
    float* xs = (float*)(smraw + DF * HID * 4);  // 2 warps * 64 rows * 17 floats

    int t = threadIdx.x;
    int w = t >> 5, l = t & 31;
    int lr = l >> 2;                      // sub-row 0..7
    int lc = l & 3;                       // col-quad 0..3
    float* xw = xs + w * (64 * 17);       // this warp's 64x17 tile

    {   // cooperative W load (only block-wide sync in the kernel)
        const ulonglong2* Wg = (const ulonglong2*)W1;
        ulonglong2* Ws2 = (ulonglong2*)Ws;
        #pragma unroll
        for (int i = 0; i < DF * HID / 4 / 64; i++)
            Ws2[i * 64 + t] = Wg[i * 64 + t];
    }
    __syncthreads();

    int rowbase = blockIdx.x * 128 + w * 64;
    int rowA = rowbase + l;
    int rowB = rowbase + 32 + l;

    ull accA[8], accB[8];
    #pragma unroll
    for (int p = 0; p < 8; p++) { accA[p] = 0ULL; accB[p] = 0ULL; }

    // register prefetch of chunk 0: rows rowbase + lr + 8i (i=0..7), cols lc*4..lc*4+3
    float4 r[8];
    {
        const float4 z = make_float4(0.f, 0.f, 0.f, 0.f);
        #pragma unroll
        for (int i = 0; i < 8; i++) {
            int gr = rowbase + lr + 8 * i;
            r[i] = (gr < n) ? ((const float4*)&x[(size_t)gr * DF])[lc] : z;
        }
    }

    for (int jb = 0; jb < DF; jb += 16) {
        __syncwarp();
        #pragma unroll
        for (int i = 0; i < 8; i++) {
            float* dst = xw + (lr + 8 * i) * 17 + lc * 4;
            dst[0] = r[i].x; dst[1] = r[i].y; dst[2] = r[i].z; dst[3] = r[i].w;
        }
        __syncwarp();

        if (jb + 16 < DF) {   // prefetch next chunk while computing this one
            int j2 = jb + 16;
            const float4 z = make_float4(0.f, 0.f, 0.f, 0.f);
            #pragma unroll
            for (int i = 0; i < 8; i++) {
                int gr = rowbase + lr + 8 * i;
                r[i] = (gr < n) ? ((const float4*)&x[(size_t)gr * DF + j2])[lc] : z;
            }
        }

        #pragma unroll
        for (int c = 0; c < 16; c++) {
            float xa = xw[l * 17 + c];          // scalar LDS, conflict-free
            float xb = xw[(32 + l) * 17 + c];
            ull ax, bx;
            asm("mov.b64 %0, {%1, %1};" : "=l"(ax) : "f"(xa));
            asm("mov.b64 %0, {%1, %1};" : "=l"(bx) : "f"(xb));
            const ulonglong2* wp = (const ulonglong2*)&Ws[(jb + c) * 8];
            ulonglong2 w01 = wp[0], w23 = wp[1];
            FMA2(accA[0], ax, w01.x); FMA2(accB[0], bx, w01.x);
            FMA2(accA[1], ax, w01.y); FMA2(accB[1], bx, w01.y);
            FMA2(accA[2], ax, w23.x); FMA2(accB[2], bx, w23.x);
            FMA2(accA[3], ax, w23.y); FMA2(accB[3], bx, w23.y);
            ulonglong2 w45 = wp[2], w67 = wp[3];
            FMA2(accA[4], ax, w45.x); FMA2(accB[4], bx, w45.x);
            FMA2(accA[5], ax, w45.y); FMA2(accB[5], bx, w45.y);
            FMA2(accA[6], ax, w67.x); FMA2(accB[6], bx, w67.x);
            FMA2(accA[7], ax, w67.y); FMA2(accB[7], bx, w67.y);
        }
    }

    if (rowA < n) {
        float d = g_dinv[rowA];
        ull dd;
        asm("mov.b64 %0, {%1, %1};" : "=l"(dd) : "f"(d));
        #pragma unroll
        for (int p = 0; p < 8; p++) MUL2(accA[p], accA[p], dd);
        ulonglong2* o = (ulonglong2*)&g_hx[(size_t)rowA * HID];
        o[0] = make_ulonglong2(accA[0], accA[1]);
        o[1] = make_ulonglong2(accA[2], accA[3]);
        o[2] = make_ulonglong2(accA[4], accA[5]);
        o[3] = make_ulonglong2(accA[6], accA[7]);
    }
    if (rowB < n) {
        float d = g_dinv[rowB];
        ull dd;
        asm("mov.b64 %0, {%1, %1};" : "=l"(dd) : "f"(d));
        #pragma unroll
        for (int p = 0; p < 8; p++) MUL2(accB[p], accB[p], dd);
        ulonglong2* o = (ulonglong2*)&g_hx[(size_t)rowB * HID];
        o[0] = make_ulonglong2(accB[0], accB[1]);
        o[1] = make_ulonglong2(accB[2], accB[3]);
        o[2] = make_ulonglong2(accB[4], accB[5]);
        o[3] = make_ulonglong2(accB[6], accB[7]);
    }
}

#define GEMM_SMEM (DF * HID * 4 + 2 * 64 * 17 * 4)   // 32768 + 8704 = 41472

// ---------------- 4: scanC — local scan of partials + chunk scan -> g_ptr ----------------
__global__ void k_scanC(int n) {
    __shared__ int sp[128];
    __shared__ int s[SCAN_CHUNK];
    int t = threadIdx.x % 128;
    int tid = threadIdx.x;

    if (tid < 128) sp[tid] = (tid < NB) ? g_part[tid] : 0;
    __syncthreads();
    if (tid < 128) {
        #pragma unroll
        for (int off = 1; off < 128; off <<= 1) {
            int a = (t >= off) ? sp[t - off] : 0;
            __syncthreads();
            sp[t] += a;
            __syncthreads();
        }
    } else {
        #pragma unroll
        for (int off = 1; off < 128; off <<= 1) { __syncthreads(); __syncthreads(); }
    }
    __syncthreads();
    int blockOff = (blockIdx.x > 0) ? sp[blockIdx.x - 1] : 0;

    int idx = blockIdx.x * SCAN_CHUNK + tid;
    int v = (idx < n) ? g_cnt[idx] : 0;
    s[tid] = v;
    __syncthreads();
    for (int off = 1; off < SCAN_CHUNK; off <<= 1) {
        int a = (tid >= off) ? s[tid - off] : 0;
        __syncthreads();
        s[tid] += a;
        __syncthreads();
    }
    if (idx < n) g_ptr[idx] = blockOff + s[tid] - v;
}

// ---------------- 5: build — scatter (src, w); cursor folded into g_ptr ----------------
__global__ void __launch_bounds__(256) k_build(const int* __restrict__ row,
                                               const int* __restrict__ col,
                                               const float* __restrict__ w, int E) {
    long i0 = ((long)blockIdx.x * blockDim.x + threadIdx.x) * 4;
    if (i0 >= E) return;
    if (i0 + 3 < E) {
        int4   r4 = *(const int4*)  (row + i0);
        int4   c4 = *(const int4*)  (col + i0);
        float4 w4 = *(const float4*)(w   + i0);
        int p0 = atomicAdd(&g_ptr[c4.x], 1);
        g_edge[p0] = make_int2(r4.x, __float_as_int(w4.x));
        int p1 = atomicAdd(&g_ptr[c4.y], 1);
        g_edge[p1] = make_int2(r4.y, __float_as_int(w4.y));
        int p2 = atomicAdd(&g_ptr[c4.z], 1);
        g_edge[p2] = make_int2(r4.z, __float_as_int(w4.z));
        int p3 = atomicAdd(&g_ptr[c4.w], 1);
        g_edge[p3] = make_int2(r4.w, __float_as_int(w4.w));
    } else {
        for (long k = i0; k < E; k++) {
            int pos = atomicAdd(&g_ptr[col[k]], 1);
            g_edge[pos] = make_int2(row[k], __float_as_int(w[k]));
        }
    }
}

// ---------------- 6: agg1 ----------------
__global__ void k_agg1(const float* __restrict__ bias, int n) {
    const float4* in = (const float4*)g_hx;
    int node = (blockIdx.x * blockDim.x + threadIdx.x) >> 5;
    int lane = threadIdx.x & 31;
    if (node >= n) return;

    int q  = lane & 3;
    int es = lane >> 2;
    int end   = g_ptr[node];
    int start = end - g_cnt[node];

    float4 acc = make_float4(0.f, 0.f, 0.f, 0.f);
    for (int e = start + es; e < end; e += 8) {
        int2  ev = __ldg(&g_edge[e]);
        float wv = __int_as_float(ev.y);
        float4 v = in[ev.x * 4 + q];
        acc.x += wv * v.x; acc.y += wv * v.y; acc.z += wv * v.z; acc.w += wv * v.w;
    }
    #pragma unroll
    for (int off = 4; off < 32; off <<= 1) {
        acc.x += __shfl_down_sync(0xffffffffu, acc.x, off);
        acc.y += __shfl_down_sync(0xffffffffu, acc.y, off);
        acc.z += __shfl_down_sync(0xffffffffu, acc.z, off);
        acc.w += __shfl_down_sync(0xffffffffu, acc.w, off);
    }
    if (lane < 4) {
        float d = g_dinv[node];
        float4 sv = in[node * 4 + lane];
        float4 b = ((const float4*)bias)[lane];
        acc.x = d * fmaxf(d * (acc.x + sv.x) + b.x, 0.f);
        acc.y = d * fmaxf(d * (acc.y + sv.y) + b.y, 0.f);
        acc.z = d * fmaxf(d * (acc.z + sv.z) + b.z, 0.f);
        acc.w = d * fmaxf(d * (acc.w + sv.w) + b.w, 0.f);
        ((float4*)g_h1)[node * 4 + lane] = acc;
    }
}

// ---------------- 7: agg2 + output GEMM ----------------
__global__ void k_agg2_out(float* __restrict__ out, const float* __restrict__ W2,
                           const float* __restrict__ b2, int n) {
    __shared__ float W2s[HID * NC];
    __shared__ float b2s[NC];
    int tid = threadIdx.x;
    for (int i = tid; i < HID * NC; i += blockDim.x) W2s[i] = W2[i];
    if (tid < NC) b2s[tid] = b2[tid];
    __syncthreads();

    const float4* in = (const float4*)g_h1;
    int node = (blockIdx.x * blockDim.x + tid) >> 5;
    int lane = tid & 31;
    if (node >= n) return;

    int q  = lane & 3;
    int es = lane >> 2;
    int end   = g_ptr[node];
    int start = end - g_cnt[node];

    float4 acc = make_float4(0.f, 0.f, 0.f, 0.f);
    for (int e = start + es; e < end; e += 8) {
        int2  ev = __ldg(&g_edge[e]);
        float wv = __int_as_float(ev.y);
        float4 v = in[ev.x * 4 + q];
        acc.x += wv * v.x; acc.y += wv * v.y; acc.z += wv * v.z; acc.w += wv * v.w;
    }
    #pragma unroll
    for (int off = 4; off < 32; off <<= 1) {
        acc.x += __shfl_down_sync(0xffffffffu, acc.x, off);
        acc.y += __shfl_down_sync(0xffffffffu, acc.y, off);
        acc.z += __shfl_down_sync(0xffffffffu, acc.z, off);
        acc.w += __shfl_down_sync(0xffffffffu, acc.w, off);
    }
    if (lane < 4) {
        float d = g_dinv[node];
        float4 sv = in[node * 4 + lane];
        acc.x = d * (acc.x + sv.x);
        acc.y = d * (acc.y + sv.y);
        acc.z = d * (acc.z + sv.z);
        acc.w = d * (acc.w + sv.w);
    }
    float h[16];
    #pragma unroll
    for (int s = 0; s < 4; s++) {
        h[4 * s + 0] = __shfl_sync(0xffffffffu, acc.x, s);
        h[4 * s + 1] = __shfl_sync(0xffffffffu, acc.y, s);
        h[4 * s + 2] = __shfl_sync(0xffffffffu, acc.z, s);
        h[4 * s + 3] = __shfl_sync(0xffffffffu, acc.w, s);
    }
    if (lane < NC / 2) {
        int c = 2 * lane;
        float s0 = b2s[c], s1 = b2s[c + 1];
        #pragma unroll
        for (int k = 0; k < HID; k++) {
            s0 += h[k] * W2s[k * NC + c];
            s1 += h[k] * W2s[k * NC + c + 1];
        }
        ((float2*)&out[node * NC])[lane] = make_float2(s0, s1);
    }
}

// ---------------- launch ----------------
extern "C" void kernel_launch(void* const* d_in, const int* in_sizes, int n_in,
                              void* d_out, int out_size) {
    const float* x  = (const float*)d_in[0];
    const int*   ei = (const int*)  d_in[1];
    const float* ew = (const float*)d_in[2];
    const float* W1 = (const float*)d_in[3];
    const float* b1 = (const float*)d_in[4];
    const float* W2 = (const float*)d_in[5];
    const float* b2 = (const float*)d_in[6];

    int E = in_sizes[2];
    int n = in_sizes[0] / DF;
    const int* rowp = ei;
    const int* colp = ei + E;

    int nb256 = (n + 255) / 256;
    int eb4   = (int)(((long)E + 1023) / 1024);

    static int smem_set = 0;
    if (!smem_set) {
        cudaFuncSetAttribute(k_gemm1, cudaFuncAttributeMaxDynamicSharedMemorySize, GEMM_SMEM);
        smem_set = 1;
    }

    k_init  <<<nb256, 256>>>(n);                          // 0
    k_pass1 <<<eb4, 256>>>(colp, ew, E);                  // 1
    k_scanA <<<NB, 256>>>(n);                             // 2
    k_gemm1 <<<(n + 127) / 128, 64, GEMM_SMEM>>>(x, W1, n); // 3  <- profiled
    k_scanC <<<NB, SCAN_CHUNK>>>(n);                      // 4
    k_build <<<eb4, 256>>>(rowp, colp, ew, E);            // 5
    long wthreads = (long)n * 32;
    int aggblocks = (int)((wthreads + 255) / 256);
    k_agg1     <<<aggblocks, 256>>>(b1, n);               // 6
    k_agg2_out <<<aggblocks, 256>>>((float*)d_out, W2, b2, n); // 7
}

// round 12
// speedup vs baseline: 1.1833x; 1.1833x over previous
#include <cuda_runtime.h>

#define NN 100000
#define NE 3200000
#define DF 512
#define HID 16
#define NC  40
#define SCAN_CHUNK 1024
#define NB ((NN + SCAN_CHUNK - 1) / SCAN_CHUNK)   // 98

typedef unsigned long long ull;

// ---------------- device scratch ----------------
__device__ ull   g_pack[NN];   // (cnt << 40) | fixed20(weighted degree)
__device__ float g_dinv[NN];   // d^-1/2
__device__ int   g_cnt[NN];    // in-degree (edges only)
__device__ int   g_ptr[NN];    // CSR offsets; after build: end offsets
__device__ int2  g_edge[NE];   // (src, w-as-int) per CSR slot
__device__ float g_hx [NN * HID];
__device__ float g_h1 [NN * HID];
__device__ int   g_part[NB];

#define FMA2(d, a, b) asm("fma.rn.f32x2 %0, %1, %2, %0;" : "+l"(d) : "l"(a), "l"(b))

// ---------------- 0: init ----------------
__global__ void k_init(int n) {
    int i = blockIdx.x * blockDim.x + threadIdx.x;
    if (i < n) g_pack[i] = (1ULL << 20);   // self-loop w=1.0 in fixed20, cnt=0
}

// ---------------- 1: pass1 — single packed 64-bit atomic per edge ----------------
__global__ void __launch_bounds__(256) k_pass1(const int* __restrict__ col,
                                               const float* __restrict__ w, int E) {
    long i0 = ((long)blockIdx.x * blockDim.x + threadIdx.x) * 4;
    if (i0 >= E) return;
    if (i0 + 3 < E) {
        int4   c4 = *(const int4*)  (col + i0);
        float4 w4 = *(const float4*)(w   + i0);
        atomicAdd(&g_pack[c4.x], (1ULL << 40) + (ull)(w4.x * 1048576.0f + 0.5f));
        atomicAdd(&g_pack[c4.y], (1ULL << 40) + (ull)(w4.y * 1048576.0f + 0.5f));
        atomicAdd(&g_pack[c4.z], (1ULL << 40) + (ull)(w4.z * 1048576.0f + 0.5f));
        atomicAdd(&g_pack[c4.w], (1ULL << 40) + (ull)(w4.w * 1048576.0f + 0.5f));
    } else {
        for (long k = i0; k < E; k++)
            atomicAdd(&g_pack[col[k]], (1ULL << 40) + (ull)(w[k] * 1048576.0f + 0.5f));
    }
}

// ---------------- 2: scanA — unpack, rsqrt, per-chunk sums ----------------
__global__ void k_scanA(int n) {
    __shared__ int sh[256];
    int t = threadIdx.x;
    int base = blockIdx.x * SCAN_CHUNK;
    int s = 0;
    #pragma unroll
    for (int k = 0; k < 4; k++) {
        int idx = base + t + k * 256;
        if (idx < n) {
            ull p = g_pack[idx];
            int cnt = (int)(p >> 40);
            float deg = (float)(p & ((1ULL << 40) - 1)) * (1.0f / 1048576.0f);
            g_cnt[idx]  = cnt;
            g_dinv[idx] = rsqrtf(deg);
            s += cnt;
        }
    }
    sh[t] = s;
    __syncthreads();
    for (int off = 128; off > 0; off >>= 1) {
        if (t < off) sh[t] += sh[t + off];
        __syncthreads();
    }
    if (t == 0) g_part[blockIdx.x] = sh[0];
}

// ---------------- 3: GEMM1 (PROFILED) — g_hx = dinv[row] * (x @ W1) ----------------
// 256 threads = 8 warps, K-SPLIT: warps 0-3 do k[0,256) for row-groups 0-3,
// warps 4-7 do k[256,512) for the same row-groups. R=2 rows/thread (64 rows/warp,
// 256 rows/block, grid 391). High warps dump partials to their x tile; one
// __syncthreads; low warps reduce + scale + store. All 4 SMSPs populated.
__global__ void __launch_bounds__(256) k_gemm1(const float* __restrict__ x,
                                               const float* __restrict__ W1, int n) {
    extern __shared__ char smraw[];
    ull*   Ws = (ull*)smraw;                     // 32 KB: Ws[k*8+p] = W1[k*16+2p..2p+1]
    float* xs = (float*)(smraw + DF * HID * 4);  // 8 warps * 64 rows * 17 floats

    int t = threadIdx.x;
    int w = t >> 5, l = t & 31;
    int g  = w & 3;                       // row group 0..3
    int kh = w >> 2;                      // k half 0/1
    int kbase = kh * 256;
    int lr = l >> 2;                      // sub-row 0..7
    int lc = l & 3;                       // col-quad 0..3
    float* xw = xs + w * (64 * 17);       // this warp's 64x17 tile

    {   // cooperative W load
        const ulonglong2* Wg = (const ulonglong2*)W1;
        ulonglong2* Ws2 = (ulonglong2*)Ws;
        #pragma unroll
        for (int i = 0; i < DF * HID / 4 / 256; i++)
            Ws2[i * 256 + t] = Wg[i * 256 + t];
    }
    __syncthreads();

    int rowbase = blockIdx.x * 256 + g * 64;
    int rowA = rowbase + l;
    int rowB = rowbase + 32 + l;

    ull accA[8], accB[8];
    #pragma unroll
    for (int p = 0; p < 8; p++) { accA[p] = 0ULL; accB[p] = 0ULL; }

    // register prefetch of chunk 0: rows rowbase + lr + 8i, cols kbase + lc*4 ..
    float4 r[8];
    {
        const float4 z = make_float4(0.f, 0.f, 0.f, 0.f);
        #pragma unroll
        for (int i = 0; i < 8; i++) {
            int gr = rowbase + lr + 8 * i;
            r[i] = (gr < n) ? ((const float4*)&x[(size_t)gr * DF + kbase])[lc] : z;
        }
    }

    for (int jb = 0; jb < 256; jb += 16) {
        __syncwarp();
        #pragma unroll
        for (int i = 0; i < 8; i++) {
            float* dst = xw + (lr + 8 * i) * 17 + lc * 4;
            dst[0] = r[i].x; dst[1] = r[i].y; dst[2] = r[i].z; dst[3] = r[i].w;
        }
        __syncwarp();

        if (jb + 16 < 256) {   // prefetch next chunk while computing this one
            int j2 = kbase + jb + 16;
            const float4 z = make_float4(0.f, 0.f, 0.f, 0.f);
            #pragma unroll
            for (int i = 0; i < 8; i++) {
                int gr = rowbase + lr + 8 * i;
                r[i] = (gr < n) ? ((const float4*)&x[(size_t)gr * DF + j2])[lc] : z;
            }
        }

        #pragma unroll
        for (int c = 0; c < 16; c++) {
            float xa = xw[l * 17 + c];          // scalar LDS, conflict-free
            float xb = xw[(32 + l) * 17 + c];
            ull ax, bx;
            asm("mov.b64 %0, {%1, %1};" : "=l"(ax) : "f"(xa));
            asm("mov.b64 %0, {%1, %1};" : "=l"(bx) : "f"(xb));
            const ulonglong2* wp = (const ulonglong2*)&Ws[(kbase + jb + c) * 8];
            ulonglong2 w01 = wp[0], w23 = wp[1];
            FMA2(accA[0], ax, w01.x); FMA2(accB[0], bx, w01.x);
            FMA2(accA[1], ax, w01.y); FMA2(accB[1], bx, w01.y);
            FMA2(accA[2], ax, w23.x); FMA2(accB[2], bx, w23.x);
            FMA2(accA[3], ax, w23.y); FMA2(accB[3], bx, w23.y);
            ulonglong2 w45 = wp[2], w67 = wp[3];
            FMA2(accA[4], ax, w45.x); FMA2(accB[4], bx, w45.x);
            FMA2(accA[5], ax, w45.y); FMA2(accB[5], bx, w45.y);
            FMA2(accA[6], ax, w67.x); FMA2(accB[6], bx, w67.x);
            FMA2(accA[7], ax, w67.y); FMA2(accB[7], bx, w67.y);
        }
    }

    // ---- K-split reduction ----
    if (kh == 1) {
        // dump partials into this warp's tile: row slot = 16 floats (64B, aligned)
        ulonglong2* dA = (ulonglong2*)(xw + l * 16);
        dA[0] = make_ulonglong2(accA[0], accA[1]);
        dA[1] = make_ulonglong2(accA[2], accA[3]);
        dA[2] = make_ulonglong2(accA[4], accA[5]);
        dA[3] = make_ulonglong2(accA[6], accA[7]);
        ulonglong2* dB = (ulonglong2*)(xw + (32 + l) * 16);
        dB[0] = make_ulonglong2(accB[0], accB[1]);
        dB[1] = make_ulonglong2(accB[2], accB[3]);
        dB[2] = make_ulonglong2(accB[4], accB[5]);
        dB[3] = make_ulonglong2(accB[6], accB[7]);
    }
    __syncthreads();
    if (kh == 0) {
        const float* part = xs + (w + 4) * (64 * 17);
        if (rowA < n) {
            float d = g_dinv[rowA];
            float o[16];
            #pragma unroll
            for (int p = 0; p < 8; p++) {
                float lo = __int_as_float((unsigned)(accA[p] & 0xffffffffu));
                float hi = __int_as_float((unsigned)(accA[p] >> 32));
                o[2 * p]     = d * (lo + part[l * 16 + 2 * p]);
                o[2 * p + 1] = d * (hi + part[l * 16 + 2 * p + 1]);
            }
            float4* og = (float4*)&g_hx[(size_t)rowA * HID];
            og[0] = make_float4(o[0],  o[1],  o[2],  o[3]);
            og[1] = make_float4(o[4],  o[5],  o[6],  o[7]);
            og[2] = make_float4(o[8],  o[9],  o[10], o[11]);
            og[3] = make_float4(o[12], o[13], o[14], o[15]);
        }
        if (rowB < n) {
            float d = g_dinv[rowB];
            float o[16];
            #pragma unroll
            for (int p = 0; p < 8; p++) {
                float lo = __int_as_float((unsigned)(accB[p] & 0xffffffffu));
                float hi = __int_as_float((unsigned)(accB[p] >> 32));
                o[2 * p]     = d * (lo + part[(32 + l) * 16 + 2 * p]);
                o[2 * p + 1] = d * (hi + part[(32 + l) * 16 + 2 * p + 1]);
            }
            float4* og = (float4*)&g_hx[(size_t)rowB * HID];
            og[0] = make_float4(o[0],  o[1],  o[2],  o[3]);
            og[1] = make_float4(o[4],  o[5],  o[6],  o[7]);
            og[2] = make_float4(o[8],  o[9],  o[10], o[11]);
            og[3] = make_float4(o[12], o[13], o[14], o[15]);
        }
    }
}

#define GEMM_SMEM (DF * HID * 4 + 8 * 64 * 17 * 4)   // 32768 + 34816 = 67584

// ---------------- 4: scanC — local scan of partials + chunk scan -> g_ptr ----------------
__global__ void k_scanC(int n) {
    __shared__ int sp[128];
    __shared__ int s[SCAN_CHUNK];
    int t = threadIdx.x % 128;
    int tid = threadIdx.x;

    if (tid < 128) sp[tid] = (tid < NB) ? g_part[tid] : 0;
    __syncthreads();
    if (tid < 128) {
        #pragma unroll
        for (int off = 1; off < 128; off <<= 1) {
            int a = (t >= off) ? sp[t - off] : 0;
            __syncthreads();
            sp[t] += a;
            __syncthreads();
        }
    } else {
        #pragma unroll
        for (int off = 1; off < 128; off <<= 1) { __syncthreads(); __syncthreads(); }
    }
    __syncthreads();
    int blockOff = (blockIdx.x > 0) ? sp[blockIdx.x - 1] : 0;

    int idx = blockIdx.x * SCAN_CHUNK + tid;
    int v = (idx < n) ? g_cnt[idx] : 0;
    s[tid] = v;
    __syncthreads();
    for (int off = 1; off < SCAN_CHUNK; off <<= 1) {
        int a = (tid >= off) ? s[tid - off] : 0;
        __syncthreads();
        s[tid] += a;
        __syncthreads();
    }
    if (idx < n) g_ptr[idx] = blockOff + s[tid] - v;
}

// ---------------- 5: build — scatter (src, w); cursor folded into g_ptr ----------------
__global__ void __launch_bounds__(256) k_build(const int* __restrict__ row,
                                               const int* __restrict__ col,
                                               const float* __restrict__ w, int E) {
    long i0 = ((long)blockIdx.x * blockDim.x + threadIdx.x) * 4;
    if (i0 >= E) return;
    if (i0 + 3 < E) {
        int4   r4 = *(const int4*)  (row + i0);
        int4   c4 = *(const int4*)  (col + i0);
        float4 w4 = *(const float4*)(w   + i0);
        int p0 = atomicAdd(&g_ptr[c4.x], 1);
        g_edge[p0] = make_int2(r4.x, __float_as_int(w4.x));
        int p1 = atomicAdd(&g_ptr[c4.y], 1);
        g_edge[p1] = make_int2(r4.y, __float_as_int(w4.y));
        int p2 = atomicAdd(&g_ptr[c4.z], 1);
        g_edge[p2] = make_int2(r4.z, __float_as_int(w4.z));
        int p3 = atomicAdd(&g_ptr[c4.w], 1);
        g_edge[p3] = make_int2(r4.w, __float_as_int(w4.w));
    } else {
        for (long k = i0; k < E; k++) {
            int pos = atomicAdd(&g_ptr[col[k]], 1);
            g_edge[pos] = make_int2(row[k], __float_as_int(w[k]));
        }
    }
}

// ---------------- 6: agg1 ----------------
__global__ void k_agg1(const float* __restrict__ bias, int n) {
    const float4* in = (const float4*)g_hx;
    int node = (blockIdx.x * blockDim.x + threadIdx.x) >> 5;
    int lane = threadIdx.x & 31;
    if (node >= n) return;

    int q  = lane & 3;
    int es = lane >> 2;
    int end   = g_ptr[node];
    int start = end - g_cnt[node];

    float4 acc = make_float4(0.f, 0.f, 0.f, 0.f);
    for (int e = start + es; e < end; e += 8) {
        int2  ev = __ldg(&g_edge[e]);
        float wv = __int_as_float(ev.y);
        float4 v = in[ev.x * 4 + q];
        acc.x += wv * v.x; acc.y += wv * v.y; acc.z += wv * v.z; acc.w += wv * v.w;
    }
    #pragma unroll
    for (int off = 4; off < 32; off <<= 1) {
        acc.x += __shfl_down_sync(0xffffffffu, acc.x, off);
        acc.y += __shfl_down_sync(0xffffffffu, acc.y, off);
        acc.z += __shfl_down_sync(0xffffffffu, acc.z, off);
        acc.w += __shfl_down_sync(0xffffffffu, acc.w, off);
    }
    if (lane < 4) {
        float d = g_dinv[node];
        float4 sv = in[node * 4 + lane];
        float4 b = ((const float4*)bias)[lane];
        acc.x = d * fmaxf(d * (acc.x + sv.x) + b.x, 0.f);
        acc.y = d * fmaxf(d * (acc.y + sv.y) + b.y, 0.f);
        acc.z = d * fmaxf(d * (acc.z + sv.z) + b.z, 0.f);
        acc.w = d * fmaxf(d * (acc.w + sv.w) + b.w, 0.f);
        ((float4*)g_h1)[node * 4 + lane] = acc;
    }
}

// ---------------- 7: agg2 + output GEMM ----------------
__global__ void k_agg2_out(float* __restrict__ out, const float* __restrict__ W2,
                           const float* __restrict__ b2, int n) {
    __shared__ float W2s[HID * NC];
    __shared__ float b2s[NC];
    int tid = threadIdx.x;
    for (int i = tid; i < HID * NC; i += blockDim.x) W2s[i] = W2[i];
    if (tid < NC) b2s[tid] = b2[tid];
    __syncthreads();

    const float4* in = (const float4*)g_h1;
    int node = (blockIdx.x * blockDim.x + tid) >> 5;
    int lane = tid & 31;
    if (node >= n) return;

    int q  = lane & 3;
    int es = lane >> 2;
    int end   = g_ptr[node];
    int start = end - g_cnt[node];

    float4 acc = make_float4(0.f, 0.f, 0.f, 0.f);
    for (int e = start + es; e < end; e += 8) {
        int2  ev = __ldg(&g_edge[e]);
        float wv = __int_as_float(ev.y);
        float4 v = in[ev.x * 4 + q];
        acc.x += wv * v.x; acc.y += wv * v.y; acc.z += wv * v.z; acc.w += wv * v.w;
    }
    #pragma unroll
    for (int off = 4; off < 32; off <<= 1) {
        acc.x += __shfl_down_sync(0xffffffffu, acc.x, off);
        acc.y += __shfl_down_sync(0xffffffffu, acc.y, off);
        acc.z += __shfl_down_sync(0xffffffffu, acc.z, off);
        acc.w += __shfl_down_sync(0xffffffffu, acc.w, off);
    }
    if (lane < 4) {
        float d = g_dinv[node];
        float4 sv = in[node * 4 + lane];
        acc.x = d * (acc.x + sv.x);
        acc.y = d * (acc.y + sv.y);
        acc.z = d * (acc.z + sv.z);
        acc.w = d * (acc.w + sv.w);
    }
    float h[16];
    #pragma unroll
    for (int s = 0; s < 4; s++) {
        h[4 * s + 0] = __shfl_sync(0xffffffffu, acc.x, s);
        h[4 * s + 1] = __shfl_sync(0xffffffffu, acc.y, s);
        h[4 * s + 2] = __shfl_sync(0xffffffffu, acc.z, s);
        h[4 * s + 3] = __shfl_sync(0xffffffffu, acc.w, s);
    }
    if (lane < NC / 2) {
        int c = 2 * lane;
        float s0 = b2s[c], s1 = b2s[c + 1];
        #pragma unroll
        for (int k = 0; k < HID; k++) {
            s0 += h[k] * W2s[k * NC + c];
            s1 += h[k] * W2s[k * NC + c + 1];
        }
        ((float2*)&out[node * NC])[lane] = make_float2(s0, s1);
    }
}

// ---------------- launch ----------------
extern "C" void kernel_launch(void* const* d_in, const int* in_sizes, int n_in,
                              void* d_out, int out_size) {
    const float* x  = (const float*)d_in[0];
    const int*   ei = (const int*)  d_in[1];
    const float* ew = (const float*)d_in[2];
    const float* W1 = (const float*)d_in[3];
    const float* b1 = (const float*)d_in[4];
    const float* W2 = (const float*)d_in[5];
    const float* b2 = (const float*)d_in[6];

    int E = in_sizes[2];
    int n = in_sizes[0] / DF;
    const int* rowp = ei;
    const int* colp = ei + E;

    int nb256 = (n + 255) / 256;
    int eb4   = (int)(((long)E + 1023) / 1024);

    static int smem_set = 0;
    if (!smem_set) {
        cudaFuncSetAttribute(k_gemm1, cudaFuncAttributeMaxDynamicSharedMemorySize, GEMM_SMEM);
        smem_set = 1;
    }

    k_init  <<<nb256, 256>>>(n);                          // 0
    k_pass1 <<<eb4, 256>>>(colp, ew, E);                  // 1
    k_scanA <<<NB, 256>>>(n);                             // 2
    k_gemm1 <<<(n + 255) / 256, 256, GEMM_SMEM>>>(x, W1, n); // 3  <- profiled
    k_scanC <<<NB, SCAN_CHUNK>>>(n);                      // 4
    k_build <<<eb4, 256>>>(rowp, colp, ew, E);            // 5
    long wthreads = (long)n * 32;
    int aggblocks = (int)((wthreads + 255) / 256);
    k_agg1     <<<aggblocks, 256>>>(b1, n);               // 6
    k_agg2_out <<<aggblocks, 256>>>((float*)d_out, W2, b2, n); // 7
}

// round 14
// speedup vs baseline: 1.1907x; 1.0062x over previous
#include <cuda_runtime.h>

#define NN 100000
#define NE 3200000
#define DF 512
#define HID 16
#define NC  40
#define SCAN_CHUNK 1024
#define NB ((NN + SCAN_CHUNK - 1) / SCAN_CHUNK)   // 98

typedef unsigned long long ull;

// ---------------- device scratch ----------------
__device__ ull   g_pack[NN];   // (cnt << 40) | fixed20(weighted degree)
__device__ float g_dinv[NN];   // d^-1/2
__device__ int   g_cnt[NN];    // in-degree (edges only)
__device__ int   g_ptr[NN];    // CSR offsets; after build: end offsets
__device__ int2  g_edge[NE];   // (src, norm-as-int) per CSR slot
__device__ float g_hx [NN * HID];   // x @ W1 (raw, no dinv)
__device__ float g_h1 [NN * HID];   // relu(agg1 + b1)
__device__ int   g_part[NB];

#define FMA2(d, a, b) asm("fma.rn.f32x2 %0, %1, %2, %0;" : "+l"(d) : "l"(a), "l"(b))

// ---------------- 0: init ----------------
__global__ void k_init(int n) {
    int i = blockIdx.x * blockDim.x + threadIdx.x;
    if (i < n) g_pack[i] = (1ULL << 20);   // self-loop w=1.0 in fixed20, cnt=0
}

// ---------------- 1: pass1 — single packed 64-bit atomic per edge ----------------
__global__ void __launch_bounds__(256) k_pass1(const int* __restrict__ col,
                                               const float* __restrict__ w, int E) {
    long i0 = ((long)blockIdx.x * blockDim.x + threadIdx.x) * 4;
    if (i0 >= E) return;
    if (i0 + 3 < E) {
        int4   c4 = *(const int4*)  (col + i0);
        float4 w4 = *(const float4*)(w   + i0);
        atomicAdd(&g_pack[c4.x], (1ULL << 40) + (ull)(w4.x * 1048576.0f + 0.5f));
        atomicAdd(&g_pack[c4.y], (1ULL << 40) + (ull)(w4.y * 1048576.0f + 0.5f));
        atomicAdd(&g_pack[c4.z], (1ULL << 40) + (ull)(w4.z * 1048576.0f + 0.5f));
        atomicAdd(&g_pack[c4.w], (1ULL << 40) + (ull)(w4.w * 1048576.0f + 0.5f));
    } else {
        for (long k = i0; k < E; k++)
            atomicAdd(&g_pack[col[k]], (1ULL << 40) + (ull)(w[k] * 1048576.0f + 0.5f));
    }
}

// ---------------- 2: scanA — unpack, rsqrt, per-chunk sums ----------------
__global__ void k_scanA(int n) {
    __shared__ int sh[256];
    int t = threadIdx.x;
    int base = blockIdx.x * SCAN_CHUNK;
    int s = 0;
    #pragma unroll
    for (int k = 0; k < 4; k++) {
        int idx = base + t + k * 256;
        if (idx < n) {
            ull p = g_pack[idx];
            int cnt = (int)(p >> 40);
            float deg = (float)(p & ((1ULL << 40) - 1)) * (1.0f / 1048576.0f);
            g_cnt[idx]  = cnt;
            g_dinv[idx] = rsqrtf(deg);
            s += cnt;
        }
    }
    sh[t] = s;
    __syncthreads();
    for (int off = 128; off > 0; off >>= 1) {
        if (t < off) sh[t] += sh[t + off];
        __syncthreads();
    }
    if (t == 0) g_part[blockIdx.x] = sh[0];
}

// ---------------- GEMM1 (side stream) — g_hx = x @ W1 (raw) ----------------
// 256 threads = 8 warps, K-split (warps 0-3: k[0,256), warps 4-7: k[256,512)).
// Independent of all preprocessing -> runs concurrently on a forked stream.
__global__ void __launch_bounds__(256) k_gemm1(const float* __restrict__ x,
                                               const float* __restrict__ W1, int n) {
    extern __shared__ char smraw[];
    ull*   Ws = (ull*)smraw;                     // 32 KB
    float* xs = (float*)(smraw + DF * HID * 4);  // 8 warps * 64 rows * 17 floats

    int t = threadIdx.x;
    int w = t >> 5, l = t & 31;
    int g  = w & 3;
    int kh = w >> 2;
    int kbase = kh * 256;
    int lr = l >> 2;
    int lc = l & 3;
    float* xw = xs + w * (64 * 17);

    {
        const ulonglong2* Wg = (const ulonglong2*)W1;
        ulonglong2* Ws2 = (ulonglong2*)Ws;
        #pragma unroll
        for (int i = 0; i < DF * HID / 4 / 256; i++)
            Ws2[i * 256 + t] = Wg[i * 256 + t];
    }
    __syncthreads();

    int rowbase = blockIdx.x * 256 + g * 64;
    int rowA = rowbase + l;
    int rowB = rowbase + 32 + l;

    ull accA[8], accB[8];
    #pragma unroll
    for (int p = 0; p < 8; p++) { accA[p] = 0ULL; accB[p] = 0ULL; }

    float4 r[8];
    {
        const float4 z = make_float4(0.f, 0.f, 0.f, 0.f);
        #pragma unroll
        for (int i = 0; i < 8; i++) {
            int gr = rowbase + lr + 8 * i;
            r[i] = (gr < n) ? ((const float4*)&x[(size_t)gr * DF + kbase])[lc] : z;
        }
    }

    for (int jb = 0; jb < 256; jb += 16) {
        __syncwarp();
        #pragma unroll
        for (int i = 0; i < 8; i++) {
            float* dst = xw + (lr + 8 * i) * 17 + lc * 4;
            dst[0] = r[i].x; dst[1] = r[i].y; dst[2] = r[i].z; dst[3] = r[i].w;
        }
        __syncwarp();

        if (jb + 16 < 256) {
            int j2 = kbase + jb + 16;
            const float4 z = make_float4(0.f, 0.f, 0.f, 0.f);
            #pragma unroll
            for (int i = 0; i < 8; i++) {
                int gr = rowbase + lr + 8 * i;
                r[i] = (gr < n) ? ((const float4*)&x[(size_t)gr * DF + j2])[lc] : z;
            }
        }

        #pragma unroll
        for (int c = 0; c < 16; c++) {
            float xa = xw[l * 17 + c];
            float xb = xw[(32 + l) * 17 + c];
            ull ax, bx;
            asm("mov.b64 %0, {%1, %1};" : "=l"(ax) : "f"(xa));
            asm("mov.b64 %0, {%1, %1};" : "=l"(bx) : "f"(xb));
            const ulonglong2* wp = (const ulonglong2*)&Ws[(kbase + jb + c) * 8];
            ulonglong2 w01 = wp[0], w23 = wp[1];
            FMA2(accA[0], ax, w01.x); FMA2(accB[0], bx, w01.x);
            FMA2(accA[1], ax, w01.y); FMA2(accB[1], bx, w01.y);
            FMA2(accA[2], ax, w23.x); FMA2(accB[2], bx, w23.x);
            FMA2(accA[3], ax, w23.y); FMA2(accB[3], bx, w23.y);
            ulonglong2 w45 = wp[2], w67 = wp[3];
            FMA2(accA[4], ax, w45.x); FMA2(accB[4], bx, w45.x);
            FMA2(accA[5], ax, w45.y); FMA2(accB[5], bx, w45.y);
            FMA2(accA[6], ax, w67.x); FMA2(accB[6], bx, w67.x);
            FMA2(accA[7], ax, w67.y); FMA2(accB[7], bx, w67.y);
        }
    }

    // ---- K-split reduction (no dinv scaling: hx stays raw) ----
    if (kh == 1) {
        ulonglong2* dA = (ulonglong2*)(xw + l * 16);
        dA[0] = make_ulonglong2(accA[0], accA[1]);
        dA[1] = make_ulonglong2(accA[2], accA[3]);
        dA[2] = make_ulonglong2(accA[4], accA[5]);
        dA[3] = make_ulonglong2(accA[6], accA[7]);
        ulonglong2* dB = (ulonglong2*)(xw + (32 + l) * 16);
        dB[0] = make_ulonglong2(accB[0], accB[1]);
        dB[1] = make_ulonglong2(accB[2], accB[3]);
        dB[2] = make_ulonglong2(accB[4], accB[5]);
        dB[3] = make_ulonglong2(accB[6], accB[7]);
    }
    __syncthreads();
    if (kh == 0) {
        const float* part = xs + (w + 4) * (64 * 17);
        if (rowA < n) {
            float o[16];
            #pragma unroll
            for (int p = 0; p < 8; p++) {
                float lo = __int_as_float((unsigned)(accA[p] & 0xffffffffu));
                float hi = __int_as_float((unsigned)(accA[p] >> 32));
                o[2 * p]     = lo + part[l * 16 + 2 * p];
                o[2 * p + 1] = hi + part[l * 16 + 2 * p + 1];
            }
            float4* og = (float4*)&g_hx[(size_t)rowA * HID];
            og[0] = make_float4(o[0],  o[1],  o[2],  o[3]);
            og[1] = make_float4(o[4],  o[5],  o[6],  o[7]);
            og[2] = make_float4(o[8],  o[9],  o[10], o[11]);
            og[3] = make_float4(o[12], o[13], o[14], o[15]);
        }
        if (rowB < n) {
            float o[16];
            #pragma unroll
            for (int p = 0; p < 8; p++) {
                float lo = __int_as_float((unsigned)(accB[p] & 0xffffffffu));
                float hi = __int_as_float((unsigned)(accB[p] >> 32));
                o[2 * p]     = lo + part[(32 + l) * 16 + 2 * p];
                o[2 * p + 1] = hi + part[(32 + l) * 16 + 2 * p + 1];
            }
            float4* og = (float4*)&g_hx[(size_t)rowB * HID];
            og[0] = make_float4(o[0],  o[1],  o[2],  o[3]);
            og[1] = make_float4(o[4],  o[5],  o[6],  o[7]);
            og[2] = make_float4(o[8],  o[9],  o[10], o[11]);
            og[3] = make_float4(o[12], o[13], o[14], o[15]);
        }
    }
}

#define GEMM_SMEM (DF * HID * 4 + 8 * 64 * 17 * 4)   // 67584

// ---------------- scanC — local scan of partials + chunk scan -> g_ptr ----------------
__global__ void k_scanC(int n) {
    __shared__ int sp[128];
    __shared__ int s[SCAN_CHUNK];
    int t = threadIdx.x % 128;
    int tid = threadIdx.x;

    if (tid < 128) sp[tid] = (tid < NB) ? g_part[tid] : 0;
    __syncthreads();
    if (tid < 128) {
        #pragma unroll
        for (int off = 1; off < 128; off <<= 1) {
            int a = (t >= off) ? sp[t - off] : 0;
            __syncthreads();
            sp[t] += a;
            __syncthreads();
        }
    } else {
        #pragma unroll
        for (int off = 1; off < 128; off <<= 1) { __syncthreads(); __syncthreads(); }
    }
    __syncthreads();
    int blockOff = (blockIdx.x > 0) ? sp[blockIdx.x - 1] : 0;

    int idx = blockIdx.x * SCAN_CHUNK + tid;
    int v = (idx < n) ? g_cnt[idx] : 0;
    s[tid] = v;
    __syncthreads();
    for (int off = 1; off < SCAN_CHUNK; off <<= 1) {
        int a = (tid >= off) ? s[tid - off] : 0;
        __syncthreads();
        s[tid] += a;
        __syncthreads();
    }
    if (idx < n) g_ptr[idx] = blockOff + s[tid] - v;
}

// ---------------- build — scatter (src, norm); cursor folded into g_ptr ----------------
__global__ void __launch_bounds__(256) k_build(const int* __restrict__ row,
                                               const int* __restrict__ col,
                                               const float* __restrict__ w, int E) {
    long i0 = ((long)blockIdx.x * blockDim.x + threadIdx.x) * 4;
    if (i0 >= E) return;
    if (i0 + 3 < E) {
        int4   r4 = *(const int4*)  (row + i0);
        int4   c4 = *(const int4*)  (col + i0);
        float4 w4 = *(const float4*)(w   + i0);
        {
            float nv = g_dinv[r4.x] * w4.x * g_dinv[c4.x];
            int p = atomicAdd(&g_ptr[c4.x], 1);
            g_edge[p] = make_int2(r4.x, __float_as_int(nv));
        }
        {
            float nv = g_dinv[r4.y] * w4.y * g_dinv[c4.y];
            int p = atomicAdd(&g_ptr[c4.y], 1);
            g_edge[p] = make_int2(r4.y, __float_as_int(nv));
        }
        {
            float nv = g_dinv[r4.z] * w4.z * g_dinv[c4.z];
            int p = atomicAdd(&g_ptr[c4.z], 1);
            g_edge[p] = make_int2(r4.z, __float_as_int(nv));
        }
        {
            float nv = g_dinv[r4.w] * w4.w * g_dinv[c4.w];
            int p = atomicAdd(&g_ptr[c4.w], 1);
            g_edge[p] = make_int2(r4.w, __float_as_int(nv));
        }
    } else {
        for (long k = i0; k < E; k++) {
            int r = row[k], c = col[k];
            float nv = g_dinv[r] * w[k] * g_dinv[c];
            int p = atomicAdd(&g_ptr[c], 1);
            g_edge[p] = make_int2(r, __float_as_int(nv));
        }
    }
}

// ---------------- agg1 — g_h1 = relu(Σ nrm·hx[src] + d²·hx[self] + b1) ----------------
__global__ void k_agg1(const float* __restrict__ bias, int n) {
    const float4* in = (const float4*)g_hx;
    int node = (blockIdx.x * blockDim.x + threadIdx.x) >> 5;
    int lane = threadIdx.x & 31;
    if (node >= n) return;

    int q  = lane & 3;
    int es = lane >> 2;
    int end   = g_ptr[node];
    int start = end - g_cnt[node];

    float4 acc = make_float4(0.f, 0.f, 0.f, 0.f);
    for (int e = start + es; e < end; e += 8) {
        int2  ev = __ldg(&g_edge[e]);
        float nv = __int_as_float(ev.y);
        float4 v = in[ev.x * 4 + q];
        acc.x += nv * v.x; acc.y += nv * v.y; acc.z += nv * v.z; acc.w += nv * v.w;
    }
    #pragma unroll
    for (int off = 4; off < 32; off <<= 1) {
        acc.x += __shfl_down_sync(0xffffffffu, acc.x, off);
        acc.y += __shfl_down_sync(0xffffffffu, acc.y, off);
        acc.z += __shfl_down_sync(0xffffffffu, acc.z, off);
        acc.w += __shfl_down_sync(0xffffffffu, acc.w, off);
    }
    if (lane < 4) {
        float d  = g_dinv[node];
        float d2 = d * d;
        float4 sv = in[node * 4 + lane];
        float4 b = ((const float4*)bias)[lane];
        acc.x = fmaxf(acc.x + d2 * sv.x + b.x, 0.f);
        acc.y = fmaxf(acc.y + d2 * sv.y + b.y, 0.f);
        acc.z = fmaxf(acc.z + d2 * sv.z + b.z, 0.f);
        acc.w = fmaxf(acc.w + d2 * sv.w + b.w, 0.f);
        ((float4*)g_h1)[node * 4 + lane] = acc;
    }
}

// ---------------- agg2 + output GEMM ----------------
__global__ void k_agg2_out(float* __restrict__ out, const float* __restrict__ W2,
                           const float* __restrict__ b2, int n) {
    __shared__ float W2s[HID * NC];
    __shared__ float b2s[NC];
    int tid = threadIdx.x;
    for (int i = tid; i < HID * NC; i += blockDim.x) W2s[i] = W2[i];
    if (tid < NC) b2s[tid] = b2[tid];
    __syncthreads();

    const float4* in = (const float4*)g_h1;
    int node = (blockIdx.x * blockDim.x + tid) >> 5;
    int lane = tid & 31;
    if (node >= n) return;

    int q  = lane & 3;
    int es = lane >> 2;
    int end   = g_ptr[node];
    int start = end - g_cnt[node];

    float4 acc = make_float4(0.f, 0.f, 0.f, 0.f);
    for (int e = start + es; e < end; e += 8) {
        int2  ev = __ldg(&g_edge[e]);
        float nv = __int_as_float(ev.y);
        float4 v = in[ev.x * 4 + q];
        acc.x += nv * v.x; acc.y += nv * v.y; acc.z += nv * v.z; acc.w += nv * v.w;
    }
    #pragma unroll
    for (int off = 4; off < 32; off <<= 1) {
        acc.x += __shfl_down_sync(0xffffffffu, acc.x, off);
        acc.y += __shfl_down_sync(0xffffffffu, acc.y, off);
        acc.z += __shfl_down_sync(0xffffffffu, acc.z, off);
        acc.w += __shfl_down_sync(0xffffffffu, acc.w, off);
    }
    if (lane < 4) {
        float d  = g_dinv[node];
        float d2 = d * d;
        float4 sv = in[node * 4 + lane];
        acc.x += d2 * sv.x;
        acc.y += d2 * sv.y;
        acc.z += d2 * sv.z;
        acc.w += d2 * sv.w;
    }
    float h[16];
    #pragma unroll
    for (int s = 0; s < 4; s++) {
        h[4 * s + 0] = __shfl_sync(0xffffffffu, acc.x, s);
        h[4 * s + 1] = __shfl_sync(0xffffffffu, acc.y, s);
        h[4 * s + 2] = __shfl_sync(0xffffffffu, acc.z, s);
        h[4 * s + 3] = __shfl_sync(0xffffffffu, acc.w, s);
    }
    if (lane < NC / 2) {
        int c = 2 * lane;
        float s0 = b2s[c], s1 = b2s[c + 1];
        #pragma unroll
        for (int k = 0; k < HID; k++) {
            s0 += h[k] * W2s[k * NC + c];
            s1 += h[k] * W2s[k * NC + c + 1];
        }
        ((float2*)&out[node * NC])[lane] = make_float2(s0, s1);
    }
}

// ---------------- launch: fork gemm1 onto a side stream ----------------
extern "C" void kernel_launch(void* const* d_in, const int* in_sizes, int n_in,
                              void* d_out, int out_size) {
    const float* x  = (const float*)d_in[0];
    const int*   ei = (const int*)  d_in[1];
    const float* ew = (const float*)d_in[2];
    const float* W1 = (const float*)d_in[3];
    const float* b1 = (const float*)d_in[4];
    const float* W2 = (const float*)d_in[5];
    const float* b2 = (const float*)d_in[6];

    int E = in_sizes[2];
    int n = in_sizes[0] / DF;
    const int* rowp = ei;
    const int* colp = ei + E;

    int nb256 = (n + 255) / 256;
    int eb4   = (int)(((long)E + 1023) / 1024);

    static cudaStream_t sG = nullptr;
    static cudaEvent_t evFork = nullptr, evJoin = nullptr;
    if (!sG) {
        cudaFuncSetAttribute(k_gemm1, cudaFuncAttributeMaxDynamicSharedMemorySize, GEMM_SMEM);
        cudaStreamCreateWithFlags(&sG, cudaStreamNonBlocking);
        cudaEventCreateWithFlags(&evFork, cudaEventDisableTiming);
        cudaEventCreateWithFlags(&evJoin, cudaEventDisableTiming);
    }

    // fork: gemm1 (independent of graph preprocessing) on side stream
    cudaEventRecord(evFork, 0);
    cudaStreamWaitEvent(sG, evFork, 0);
    k_gemm1<<<(n + 255) / 256, 256, GEMM_SMEM, sG>>>(x, W1, n);
    cudaEventRecord(evJoin, sG);

    // main chain: preprocessing
    k_init  <<<nb256, 256>>>(n);
    k_pass1 <<<eb4, 256>>>(colp, ew, E);
    k_scanA <<<NB, 256>>>(n);
    k_scanC <<<NB, SCAN_CHUNK>>>(n);
    k_build <<<eb4, 256>>>(rowp, colp, ew, E);

    // join: aggregation needs both g_hx and the CSR
    cudaStreamWaitEvent(0, evJoin, 0);
    long wthreads = (long)n * 32;
    int aggblocks = (int)((wthreads + 255) / 256);
    k_agg1     <<<aggblocks, 256>>>(b1, n);
    k_agg2_out <<<aggblocks, 256>>>((float*)d_out, W2, b2, n);
}

// round 16
// speedup vs baseline: 1.2595x; 1.0578x over previous
#include <cuda_runtime.h>

#define NN 100000
#define NE 3200000
#define DF 512
#define HID 16
#define NC  40
#define SCAN_CHUNK 1024
#define NB ((NN + SCAN_CHUNK - 1) / SCAN_CHUNK)   // 98

typedef unsigned long long ull;

// ---------------- device scratch ----------------
__device__ ull   g_pack[NN];   // (cnt << 40) | fixed20(weighted degree); ZERO between calls
__device__ float g_dinv[NN];   // d^-1/2
__device__ int   g_cnt[NN];    // in-degree (edges only)
__device__ int   g_ptr[NN];    // CSR offsets; after build: end offsets
__device__ int2  g_edge[NE];   // (src, norm-as-int) per CSR slot
__device__ float g_hx [NN * HID];   // x @ W1 (raw)
__device__ float g_h1 [NN * HID];   // relu(agg1 + b1)
__device__ int   g_part[NB];

#define FMA2(d, a, b) asm("fma.rn.f32x2 %0, %1, %2, %0;" : "+l"(d) : "l"(a), "l"(b))

// ---------------- pass1 — single packed 64-bit atomic per edge (g_pack starts 0) ----------------
__global__ void __launch_bounds__(256) k_pass1(const int* __restrict__ col,
                                               const float* __restrict__ w, int E) {
    long i0 = ((long)blockIdx.x * blockDim.x + threadIdx.x) * 4;
    if (i0 >= E) return;
    if (i0 + 3 < E) {
        int4   c4 = *(const int4*)  (col + i0);
        float4 w4 = *(const float4*)(w   + i0);
        atomicAdd(&g_pack[c4.x], (1ULL << 40) + (ull)(w4.x * 1048576.0f + 0.5f));
        atomicAdd(&g_pack[c4.y], (1ULL << 40) + (ull)(w4.y * 1048576.0f + 0.5f));
        atomicAdd(&g_pack[c4.z], (1ULL << 40) + (ull)(w4.z * 1048576.0f + 0.5f));
        atomicAdd(&g_pack[c4.w], (1ULL << 40) + (ull)(w4.w * 1048576.0f + 0.5f));
    } else {
        for (long k = i0; k < E; k++)
            atomicAdd(&g_pack[col[k]], (1ULL << 40) + (ull)(w[k] * 1048576.0f + 0.5f));
    }
}

// ---------------- scanA — unpack (+self-loop 1.0), rsqrt, per-chunk sums, re-zero g_pack ----------------
__global__ void k_scanA(int n) {
    __shared__ int sh[256];
    int t = threadIdx.x;
    int base = blockIdx.x * SCAN_CHUNK;
    int s = 0;
    #pragma unroll
    for (int k = 0; k < 4; k++) {
        int idx = base + t + k * 256;
        if (idx < n) {
            ull p = g_pack[idx];
            g_pack[idx] = 0ULL;             // restore invariant for next graph replay
            int cnt = (int)(p >> 40);
            float deg = 1.0f + (float)(p & ((1ULL << 40) - 1)) * (1.0f / 1048576.0f);
            g_cnt[idx]  = cnt;
            g_dinv[idx] = rsqrtf(deg);
            s += cnt;
        }
    }
    sh[t] = s;
    __syncthreads();
    for (int off = 128; off > 0; off >>= 1) {
        if (t < off) sh[t] += sh[t + off];
        __syncthreads();
    }
    if (t == 0) g_part[blockIdx.x] = sh[0];
}

// ---------------- scanC — local scan of partials + chunk scan -> g_ptr ----------------
__global__ void k_scanC(int n) {
    __shared__ int sp[128];
    __shared__ int s[SCAN_CHUNK];
    int t = threadIdx.x % 128;
    int tid = threadIdx.x;

    if (tid < 128) sp[tid] = (tid < NB) ? g_part[tid] : 0;
    __syncthreads();
    if (tid < 128) {
        #pragma unroll
        for (int off = 1; off < 128; off <<= 1) {
            int a = (t >= off) ? sp[t - off] : 0;
            __syncthreads();
            sp[t] += a;
            __syncthreads();
        }
    } else {
        #pragma unroll
        for (int off = 1; off < 128; off <<= 1) { __syncthreads(); __syncthreads(); }
    }
    __syncthreads();
    int blockOff = (blockIdx.x > 0) ? sp[blockIdx.x - 1] : 0;

    int idx = blockIdx.x * SCAN_CHUNK + tid;
    int v = (idx < n) ? g_cnt[idx] : 0;
    s[tid] = v;
    __syncthreads();
    for (int off = 1; off < SCAN_CHUNK; off <<= 1) {
        int a = (tid >= off) ? s[tid - off] : 0;
        __syncthreads();
        s[tid] += a;
        __syncthreads();
    }
    if (idx < n) g_ptr[idx] = blockOff + s[tid] - v;
}

// ---------------- build (PROFILED, 4th launch) — scatter (src, norm) ----------------
__global__ void __launch_bounds__(256) k_build(const int* __restrict__ row,
                                               const int* __restrict__ col,
                                               const float* __restrict__ w, int E) {
    long i0 = ((long)blockIdx.x * blockDim.x + threadIdx.x) * 4;
    if (i0 >= E) return;
    if (i0 + 3 < E) {
        int4   r4 = *(const int4*)  (row + i0);
        int4   c4 = *(const int4*)  (col + i0);
        float4 w4 = *(const float4*)(w   + i0);
        {
            float nv = g_dinv[r4.x] * w4.x * g_dinv[c4.x];
            int p = atomicAdd(&g_ptr[c4.x], 1);
            g_edge[p] = make_int2(r4.x, __float_as_int(nv));
        }
        {
            float nv = g_dinv[r4.y] * w4.y * g_dinv[c4.y];
            int p = atomicAdd(&g_ptr[c4.y], 1);
            g_edge[p] = make_int2(r4.y, __float_as_int(nv));
        }
        {
            float nv = g_dinv[r4.z] * w4.z * g_dinv[c4.z];
            int p = atomicAdd(&g_ptr[c4.z], 1);
            g_edge[p] = make_int2(r4.z, __float_as_int(nv));
        }
        {
            float nv = g_dinv[r4.w] * w4.w * g_dinv[c4.w];
            int p = atomicAdd(&g_ptr[c4.w], 1);
            g_edge[p] = make_int2(r4.w, __float_as_int(nv));
        }
    } else {
        for (long k = i0; k < E; k++) {
            int r = row[k], c = col[k];
            float nv = g_dinv[r] * w[k] * g_dinv[c];
            int p = atomicAdd(&g_ptr[c], 1);
            g_edge[p] = make_int2(r, __float_as_int(nv));
        }
    }
}

// ---------------- GEMM1 (side stream) — g_hx = x @ W1 (raw) ----------------
__global__ void __launch_bounds__(256) k_gemm1(const float* __restrict__ x,
                                               const float* __restrict__ W1, int n) {
    extern __shared__ char smraw[];
    ull*   Ws = (ull*)smraw;                     // 32 KB
    float* xs = (float*)(smraw + DF * HID * 4);  // 8 warps * 64 rows * 17 floats

    int t = threadIdx.x;
    int w = t >> 5, l = t & 31;
    int g  = w & 3;
    int kh = w >> 2;
    int kbase = kh * 256;
    int lr = l >> 2;
    int lc = l & 3;
    float* xw = xs + w * (64 * 17);

    {
        const ulonglong2* Wg = (const ulonglong2*)W1;
        ulonglong2* Ws2 = (ulonglong2*)Ws;
        #pragma unroll
        for (int i = 0; i < DF * HID / 4 / 256; i++)
            Ws2[i * 256 + t] = Wg[i * 256 + t];
    }
    __syncthreads();

    int rowbase = blockIdx.x * 256 + g * 64;
    int rowA = rowbase + l;
    int rowB = rowbase + 32 + l;

    ull accA[8], accB[8];
    #pragma unroll
    for (int p = 0; p < 8; p++) { accA[p] = 0ULL; accB[p] = 0ULL; }

    float4 r[8];
    {
        const float4 z = make_float4(0.f, 0.f, 0.f, 0.f);
        #pragma unroll
        for (int i = 0; i < 8; i++) {
            int gr = rowbase + lr + 8 * i;
            r[i] = (gr < n) ? ((const float4*)&x[(size_t)gr * DF + kbase])[lc] : z;
        }
    }

    for (int jb = 0; jb < 256; jb += 16) {
        __syncwarp();
        #pragma unroll
        for (int i = 0; i < 8; i++) {
            float* dst = xw + (lr + 8 * i) * 17 + lc * 4;
            dst[0] = r[i].x; dst[1] = r[i].y; dst[2] = r[i].z; dst[3] = r[i].w;
        }
        __syncwarp();

        if (jb + 16 < 256) {
            int j2 = kbase + jb + 16;
            const float4 z = make_float4(0.f, 0.f, 0.f, 0.f);
            #pragma unroll
            for (int i = 0; i < 8; i++) {
                int gr = rowbase + lr + 8 * i;
                r[i] = (gr < n) ? ((const float4*)&x[(size_t)gr * DF + j2])[lc] : z;
            }
        }

        #pragma unroll
        for (int c = 0; c < 16; c++) {
            float xa = xw[l * 17 + c];
            float xb = xw[(32 + l) * 17 + c];
            ull ax, bx;
            asm("mov.b64 %0, {%1, %1};" : "=l"(ax) : "f"(xa));
            asm("mov.b64 %0, {%1, %1};" : "=l"(bx) : "f"(xb));
            const ulonglong2* wp = (const ulonglong2*)&Ws[(kbase + jb + c) * 8];
            ulonglong2 w01 = wp[0], w23 = wp[1];
            FMA2(accA[0], ax, w01.x); FMA2(accB[0], bx, w01.x);
            FMA2(accA[1], ax, w01.y); FMA2(accB[1], bx, w01.y);
            FMA2(accA[2], ax, w23.x); FMA2(accB[2], bx, w23.x);
            FMA2(accA[3], ax, w23.y); FMA2(accB[3], bx, w23.y);
            ulonglong2 w45 = wp[2], w67 = wp[3];
            FMA2(accA[4], ax, w45.x); FMA2(accB[4], bx, w45.x);
            FMA2(accA[5], ax, w45.y); FMA2(accB[5], bx, w45.y);
            FMA2(accA[6], ax, w67.x); FMA2(accB[6], bx, w67.x);
            FMA2(accA[7], ax, w67.y); FMA2(accB[7], bx, w67.y);
        }
    }

    if (kh == 1) {
        ulonglong2* dA = (ulonglong2*)(xw + l * 16);
        dA[0] = make_ulonglong2(accA[0], accA[1]);
        dA[1] = make_ulonglong2(accA[2], accA[3]);
        dA[2] = make_ulonglong2(accA[4], accA[5]);
        dA[3] = make_ulonglong2(accA[6], accA[7]);
        ulonglong2* dB = (ulonglong2*)(xw + (32 + l) * 16);
        dB[0] = make_ulonglong2(accB[0], accB[1]);
        dB[1] = make_ulonglong2(accB[2], accB[3]);
        dB[2] = make_ulonglong2(accB[4], accB[5]);
        dB[3] = make_ulonglong2(accB[6], accB[7]);
    }
    __syncthreads();
    if (kh == 0) {
        const float* part = xs + (w + 4) * (64 * 17);
        if (rowA < n) {
            float o[16];
            #pragma unroll
            for (int p = 0; p < 8; p++) {
                float lo = __int_as_float((unsigned)(accA[p] & 0xffffffffu));
                float hi = __int_as_float((unsigned)(accA[p] >> 32));
                o[2 * p]     = lo + part[l * 16 + 2 * p];
                o[2 * p + 1] = hi + part[l * 16 + 2 * p + 1];
            }
            float4* og = (float4*)&g_hx[(size_t)rowA * HID];
            og[0] = make_float4(o[0],  o[1],  o[2],  o[3]);
            og[1] = make_float4(o[4],  o[5],  o[6],  o[7]);
            og[2] = make_float4(o[8],  o[9],  o[10], o[11]);
            og[3] = make_float4(o[12], o[13], o[14], o[15]);
        }
        if (rowB < n) {
            float o[16];
            #pragma unroll
            for (int p = 0; p < 8; p++) {
                float lo = __int_as_float((unsigned)(accB[p] & 0xffffffffu));
                float hi = __int_as_float((unsigned)(accB[p] >> 32));
                o[2 * p]     = lo + part[(32 + l) * 16 + 2 * p];
                o[2 * p + 1] = hi + part[(32 + l) * 16 + 2 * p + 1];
            }
            float4* og = (float4*)&g_hx[(size_t)rowB * HID];
            og[0] = make_float4(o[0],  o[1],  o[2],  o[3]);
            og[1] = make_float4(o[4],  o[5],  o[6],  o[7]);
            og[2] = make_float4(o[8],  o[9],  o[10], o[11]);
            og[3] = make_float4(o[12], o[13], o[14], o[15]);
        }
    }
}

#define GEMM_SMEM (DF * HID * 4 + 8 * 64 * 17 * 4)   // 67584

// ---------------- agg1 — 4-lane group per node, no shuffles, unroll-2 dual acc ----------------
__global__ void __launch_bounds__(256) k_agg1(const float* __restrict__ bias, int n) {
    const float4* in = (const float4*)g_hx;
    int gid  = blockIdx.x * blockDim.x + threadIdx.x;
    int node = gid >> 2;
    int q    = gid & 3;
    if (node >= n) return;

    int end   = g_ptr[node];
    int start = end - g_cnt[node];

    float4 a0 = make_float4(0.f, 0.f, 0.f, 0.f);
    float4 a1 = make_float4(0.f, 0.f, 0.f, 0.f);
    int e = start;
    for (; e + 2 <= end; e += 2) {
        int2 e0 = __ldg(&g_edge[e]);
        int2 e1 = __ldg(&g_edge[e + 1]);
        float4 v0 = in[e0.x * 4 + q];
        float4 v1 = in[e1.x * 4 + q];
        float w0 = __int_as_float(e0.y), w1 = __int_as_float(e1.y);
        a0.x += w0 * v0.x; a0.y += w0 * v0.y; a0.z += w0 * v0.z; a0.w += w0 * v0.w;
        a1.x += w1 * v1.x; a1.y += w1 * v1.y; a1.z += w1 * v1.z; a1.w += w1 * v1.w;
    }
    if (e < end) {
        int2 e0 = __ldg(&g_edge[e]);
        float4 v0 = in[e0.x * 4 + q];
        float w0 = __int_as_float(e0.y);
        a0.x += w0 * v0.x; a0.y += w0 * v0.y; a0.z += w0 * v0.z; a0.w += w0 * v0.w;
    }
    float d  = g_dinv[node];
    float d2 = d * d;
    float4 sv = in[node * 4 + q];
    float4 b  = ((const float4*)bias)[q];
    float4 o;
    o.x = fmaxf(a0.x + a1.x + d2 * sv.x + b.x, 0.f);
    o.y = fmaxf(a0.y + a1.y + d2 * sv.y + b.y, 0.f);
    o.z = fmaxf(a0.z + a1.z + d2 * sv.z + b.z, 0.f);
    o.w = fmaxf(a0.w + a1.w + d2 * sv.w + b.w, 0.f);
    ((float4*)g_h1)[node * 4 + q] = o;
}

// ---------------- agg2 + output GEMM — group-per-node agg, smem staging, 40-class out ----------------
__global__ void __launch_bounds__(256) k_agg2_out(float* __restrict__ out,
                                                  const float* __restrict__ W2,
                                                  const float* __restrict__ b2, int n) {
    __shared__ float W2s[HID * NC];     // 2.5 KB
    __shared__ float b2s[NC];
    __shared__ float hst[8][8 * HID];   // 8 warps x (8 nodes x 16 dims) = 4 KB
    int tid = threadIdx.x;
    for (int i = tid; i < HID * NC; i += blockDim.x) W2s[i] = W2[i];
    if (tid < NC) b2s[tid] = b2[tid];
    __syncthreads();

    const float4* in = (const float4*)g_h1;
    int warp = tid >> 5, lane = tid & 31;
    int nodebase = (blockIdx.x * 8 + warp) * 8;   // 8 nodes per warp
    int ln   = lane >> 2;                          // local node 0..7
    int q    = lane & 3;
    int node = nodebase + ln;

    float4 acc = make_float4(0.f, 0.f, 0.f, 0.f);
    if (node < n) {
        int end   = g_ptr[node];
        int start = end - g_cnt[node];
        float4 a1 = make_float4(0.f, 0.f, 0.f, 0.f);
        int e = start;
        for (; e + 2 <= end; e += 2) {
            int2 e0 = __ldg(&g_edge[e]);
            int2 e1 = __ldg(&g_edge[e + 1]);
            float4 v0 = in[e0.x * 4 + q];
            float4 v1 = in[e1.x * 4 + q];
            float w0 = __int_as_float(e0.y), w1 = __int_as_float(e1.y);
            acc.x += w0 * v0.x; acc.y += w0 * v0.y; acc.z += w0 * v0.z; acc.w += w0 * v0.w;
            a1.x  += w1 * v1.x; a1.y  += w1 * v1.y; a1.z  += w1 * v1.z; a1.w  += w1 * v1.w;
        }
        if (e < end) {
            int2 e0 = __ldg(&g_edge[e]);
            float4 v0 = in[e0.x * 4 + q];
            float w0 = __int_as_float(e0.y);
            acc.x += w0 * v0.x; acc.y += w0 * v0.y; acc.z += w0 * v0.z; acc.w += w0 * v0.w;
        }
        float d  = g_dinv[node];
        float d2 = d * d;
        float4 sv = in[node * 4 + q];
        acc.x += a1.x + d2 * sv.x;
        acc.y += a1.y + d2 * sv.y;
        acc.z += a1.z + d2 * sv.z;
        acc.w += a1.w + d2 * sv.w;
    }
    *(float4*)&hst[warp][ln * HID + q * 4] = acc;
    __syncwarp();

    // 8 nodes x 40 classes = 320 outputs per warp; 10 per lane, coalesced
    #pragma unroll
    for (int k = 0; k < 10; k++) {
        int flat = k * 32 + lane;
        int l2   = flat / NC;
        int cls  = flat - l2 * NC;
        int gn   = nodebase + l2;
        if (gn < n) {
            float s = b2s[cls];
            const float* hp = &hst[warp][l2 * HID];
            #pragma unroll
            for (int h = 0; h < HID; h++) s += hp[h] * W2s[h * NC + cls];
            out[gn * NC + cls] = s;
        }
    }
}

// ---------------- launch ----------------
extern "C" void kernel_launch(void* const* d_in, const int* in_sizes, int n_in,
                              void* d_out, int out_size) {
    const float* x  = (const float*)d_in[0];
    const int*   ei = (const int*)  d_in[1];
    const float* ew = (const float*)d_in[2];
    const float* W1 = (const float*)d_in[3];
    const float* b1 = (const float*)d_in[4];
    const float* W2 = (const float*)d_in[5];
    const float* b2 = (const float*)d_in[6];

    int E = in_sizes[2];
    int n = in_sizes[0] / DF;
    const int* rowp = ei;
    const int* colp = ei + E;

    int eb4 = (int)(((long)E + 1023) / 1024);

    static cudaStream_t sG = nullptr;
    static cudaEvent_t evFork = nullptr, evJoin = nullptr;
    if (!sG) {
        cudaFuncSetAttribute(k_gemm1, cudaFuncAttributeMaxDynamicSharedMemorySize, GEMM_SMEM);
        cudaStreamCreateWithFlags(&sG, cudaStreamNonBlocking);
        cudaEventCreateWithFlags(&evFork, cudaEventDisableTiming);
        cudaEventCreateWithFlags(&evJoin, cudaEventDisableTiming);
    }

    // fork point for the independent GEMM (issued later; depends only on stream head)
    cudaEventRecord(evFork, 0);
    cudaStreamWaitEvent(sG, evFork, 0);

    // main chain: preprocessing (g_pack is zero on entry; scanA re-zeroes it)
    k_pass1 <<<eb4, 256>>>(colp, ew, E);                  // 1
    k_scanA <<<NB, 256>>>(n);                             // 2
    k_scanC <<<NB, SCAN_CHUNK>>>(n);                      // 3
    k_build <<<eb4, 256>>>(rowp, colp, ew, E);            // 4  <- profiled

    // side stream: gemm1 (executes concurrently with the chain above)
    k_gemm1<<<(n + 255) / 256, 256, GEMM_SMEM, sG>>>(x, W1, n);   // 5
    cudaEventRecord(evJoin, sG);
    cudaStreamWaitEvent(0, evJoin, 0);

    // aggregation: 4-lane group per node
    int g1blocks = (int)(((long)n * 4 + 255) / 256);
    int g2blocks = (n + 63) / 64;
    k_agg1     <<<g1blocks, 256>>>(b1, n);                // 6
    k_agg2_out <<<g2blocks, 256>>>((float*)d_out, W2, b2, n); // 7
}